// round 8
// baseline (speedup 1.0000x reference)
#include <cuda_runtime.h>
#include <math.h>

// ---------------------------------------------------------------------------
// DGCNN fused per-graph kernel, v4.
// One CTA = one graph (200 nodes, 6400 edges). 384 threads, 2 CTAs/SM.
// v4: CSR build via GMEM atomics (off the smem crossbar) + fixed-pad smem
//     staging; 24 warps/SM; 16-wide weight chunks to fit 85 regs.
// ---------------------------------------------------------------------------

#define NTHREADS 384
#define NWARPS   12

typedef unsigned long long ull;

constexpr int Bg   = 512;    // graphs
constexpr int M    = 200;    // nodes / graph
constexpr int EPG  = 6400;   // edges / graph
constexpr int DIN  = 128;
constexpr int F1   = 32;
constexpr int FP   = 100;    // padded feature row stride (16B align)
constexpr int TOPK = 30;
constexpr int DMAX = 80;     // fixed per-node staging capacity (deg ~32±5.7)

// GMEM scratch: per-graph degree counters (zeroed by each CTA per launch)
__device__ int g_cnt[Bg * M];

// Persistent SMEM layout (bytes)
constexpr int OFF_HCAT = 0;             // 200*100*4 = 80000
constexpr int OFF_XW   = 80000;         // 201*32*4  = 25728 -> 105728
constexpr int OFF_DINV = 105728;        // 200*4     -> 106528
constexpr int OFF_RP   = 106528;        // 201*4     -> pad 107344
constexpr int OFF_COL  = 107344;        // 7040      -> 114384
constexpr int SMEM_TOTAL = 114384;

// Aliases inside hcat region (dead until layer-1 agg writes hcat):
//  colFixed[200*80]  -> hcat + 0      (CSR staging, dead after pack)
//  degS[200] ints    -> hcat + 16000  (dead after pack)
//  stage             -> hcat + 17408  (layer-1 GEMM, 12 warps * 32 floats)
// Aliases inside xw region (xw used only as [201] floats by layer 4):
constexpr int OFF_TOP  = OFF_XW + 2048;   // 30 ints
constexpr int OFF_DOT  = OFF_XW + 2176;   // 480 floats
constexpr int OFF_C1P  = OFF_XW + 4096;   // 240 floats
constexpr int OFF_FLAT = OFF_XW + 5120;   // 352 floats
constexpr int OFF_HLIN = OFF_XW + 6592;   // 128 floats
constexpr int OFF_CW1S = OFF_XW + 7168;   // 16*97 floats

#define ADDX2(acc, v) \
    asm("add.rn.f32x2 %0, %0, %1;" : "+l"(acc) : "l"(v))
#define FMAX2(r, a, b, c) \
    asm("fma.rn.f32x2 %0, %1, %2, %3;" : "=l"(r) : "l"(a), "l"(b), "l"(c))

__device__ __forceinline__ ull pack2(float lo, float hi) {
    ull r;
    asm("mov.b64 %0, {%1, %2};" : "=l"(r)
        : "r"(__float_as_uint(lo)), "r"(__float_as_uint(hi)));
    return r;
}
__device__ __forceinline__ void unpack2(ull v, float& lo, float& hi) {
    unsigned a, b;
    asm("mov.b64 {%0, %1}, %2;" : "=r"(a), "=r"(b) : "l"(v));
    lo = __uint_as_float(a); hi = __uint_as_float(b);
}

__device__ __forceinline__ float warp_sum(float v) {
#pragma unroll
    for (int d = 16; d; d >>= 1) v += __shfl_xor_sync(0xffffffffu, v, d);
    return v;
}

// Half-warp f32x2 aggregation: lanes 0-15 -> node n, lanes 16-31 -> node n+1.
// Each lane owns channels (2*ln, 2*ln+1). xw pre-scaled by dinv[src].
__device__ __forceinline__ void agg32x2(
    float* __restrict__ hcat, const float* __restrict__ xw,
    const float* __restrict__ dinv, const int* __restrict__ rp,
    const unsigned char* __restrict__ col,
    const float* __restrict__ bias, int outoff, int lane, int warp)
{
    const int half = lane >> 4;
    const int ln   = lane & 15;
    const ull bb2  = *(const ull*)(bias + 2 * ln);

    for (int n = 2 * warp + half; n < M; n += 2 * NWARPS) {
        const int e0 = rp[n], e1 = rp[n + 1];
        ull a0 = *(const ull*)(xw + n * F1 + 2 * ln);   // self term
        ull a1 = 0;                                      // (0.f, 0.f)
        for (int e = e0; e < e1; e += 4) {
            uchar4 c = *(const uchar4*)(col + e);
            ADDX2(a0, *(const ull*)(xw + c.x * F1 + 2 * ln));
            ADDX2(a1, *(const ull*)(xw + c.y * F1 + 2 * ln));
            ADDX2(a0, *(const ull*)(xw + c.z * F1 + 2 * ln));
            ADDX2(a1, *(const ull*)(xw + c.w * F1 + 2 * ln));
        }
        ADDX2(a0, a1);
        float dn = dinv[n];
        ull dn2 = pack2(dn, dn);
        ull r; FMAX2(r, dn2, a0, bb2);
        float lo, hi; unpack2(r, lo, hi);
        float2 o; o.x = tanhf(lo); o.y = tanhf(hi);
        *(float2*)(hcat + n * FP + outoff + 2 * ln) = o;
    }
}

// 32->32 GEMM in two 16-wide k chunks (16 weight regs live at a time).
// Per-warp node ownership: no barrier needed between chunks.
__device__ __forceinline__ void gemm32(
    const float* __restrict__ hcat, float* __restrict__ xw,
    const float* __restrict__ dinv, const float* __restrict__ W,
    int inoff, int lane, int warp)
{
#pragma unroll
    for (int kc = 0; kc < 32; kc += 16) {
        float w[16];
#pragma unroll
        for (int k = 0; k < 16; k++) w[k] = W[(kc + k) * 32 + lane];
        for (int n = warp; n < M; n += NWARPS) {
            const float4* hr4 = (const float4*)(hcat + n * FP + inoff + kc);
            float acc = (kc == 0) ? 0.f : xw[n * F1 + lane];
#pragma unroll
            for (int q = 0; q < 4; q++) {
                float4 h = hr4[q];
                acc = fmaf(h.x, w[4 * q + 0], acc);
                acc = fmaf(h.y, w[4 * q + 1], acc);
                acc = fmaf(h.z, w[4 * q + 2], acc);
                acc = fmaf(h.w, w[4 * q + 3], acc);
            }
            if (kc == 16) acc *= dinv[n];
            xw[n * F1 + lane] = acc;
        }
    }
}

__global__ __launch_bounds__(NTHREADS, 2)
void dgcnn_kernel(
    const float* __restrict__ x,
    const int*   __restrict__ ei,       // [2, E]
    const float* __restrict__ W1, const float* __restrict__ b1,
    const float* __restrict__ W2, const float* __restrict__ b2,
    const float* __restrict__ W3, const float* __restrict__ b3,
    const float* __restrict__ W4, const float* __restrict__ b4,
    const float* __restrict__ cW1, const float* __restrict__ cb1,
    const float* __restrict__ cW2, const float* __restrict__ cb2,
    const float* __restrict__ lW1, const float* __restrict__ lb1,
    const float* __restrict__ lW2, const float* __restrict__ lb2,
    float* __restrict__ out, int Etot)
{
    extern __shared__ char smem[];
    float* hcat  = (float*)(smem + OFF_HCAT);
    float* xw    = (float*)(smem + OFF_XW);
    float* dinv  = (float*)(smem + OFF_DINV);
    int*   rp    = (int*)  (smem + OFF_RP);
    unsigned char* col = (unsigned char*)(smem + OFF_COL);
    unsigned char* colFixed = (unsigned char*)(smem);            // alias
    int*   degS  = (int*)  (smem + 16000);                       // alias
    float* stage = (float*)(smem + 17408);                       // alias
    int*   topn  = (int*)  (smem + OFF_TOP);
    float* dots  = (float*)(smem + OFF_DOT);
    float* c1p   = (float*)(smem + OFF_C1P);
    float* flat  = (float*)(smem + OFF_FLAT);
    float* hlin  = (float*)(smem + OFF_HLIN);
    float* cW1s  = (float*)(smem + OFF_CW1S);

    const int g     = blockIdx.x;
    const int tid   = threadIdx.x;
    const int lane  = tid & 31;
    const int warp  = tid >> 5;
    const int nbase = g * M;
    const int ebase = g * EPG;

    const int2* s2 = (const int2*)(ei + ebase);
    const int2* d2 = (const int2*)(ei + Etot + ebase);

    // ============ CSR build via GMEM atomics (off the smem pipe) ============
    // 1. zero my gmem counter slice
    for (int i = tid; i < M; i += NTHREADS) g_cnt[nbase + i] = 0;
    __threadfence();
    __syncthreads();

    // 2. scatter into fixed-pad smem staging; positions from L2 atomics
    for (int e2 = tid; e2 < EPG / 2; e2 += NTHREADS) {
        int2 s = s2[e2];
        int2 d = d2[e2];
        int d0 = d.x - nbase, d1 = d.y - nbase;
        int p0 = atomicAdd(&g_cnt[nbase + d0], 1);
        colFixed[d0 * DMAX + p0] = (unsigned char)(s.x - nbase);
        int p1 = atomicAdd(&g_cnt[nbase + d1], 1);
        colFixed[d1 * DMAX + p1] = (unsigned char)(s.y - nbase);
    }
    __syncthreads();   // atomics returned (results consumed) + STS drained

    // 3. degrees from L2
    for (int i = tid; i < M; i += NTHREADS) {
        int dg = __ldcg(&g_cnt[nbase + i]);
        degS[i] = dg;
        dinv[i] = rsqrtf((float)dg + 1.0f);
    }
    __syncthreads();

    // 4. rowptr: exclusive scan of 4-padded degrees (warp 0)
    if (warp == 0) {
        int run = 0;
        for (int c0 = 0; c0 < 224; c0 += 32) {
            int i = c0 + lane;
            int v = (i < M) ? ((degS[i] + 3) & ~3) : 0;
            int orig = v;
#pragma unroll
            for (int d = 1; d < 32; d <<= 1) {
                int t = __shfl_up_sync(0xffffffffu, v, d);
                if (lane >= d) v += t;
            }
            if (i < M) rp[i] = run + v - orig;
            run += __shfl_sync(0xffffffffu, v, 31);
        }
        if (lane == 0) rp[M] = run;
    }
    __syncthreads();

    // 5. pack staging -> 4-padded CSR (dummy node 200 in tails)
    for (int n = warp; n < M; n += NWARPS) {
        int dg   = degS[n];
        int base = rp[n];
        int dpad = rp[n + 1] - base;
        for (int l = lane; l < dpad; l += 32)
            col[base + l] = (l < dg) ? colFixed[n * DMAX + l]
                                     : (unsigned char)200;
    }
    if (tid < 32) xw[200 * F1 + lane] = 0.f;    // zero dummy xw row
    __syncthreads();

    // ================= layer-1 GEMM: xw' = dinv * (x[g] @ W1) ===============
    {
        const float* xg = x + (size_t)nbase * DIN;
        float* st = stage + warp * 32;
        const int half = lane >> 4, ln16 = lane & 15;
#pragma unroll
        for (int kc = 0; kc < DIN; kc += 16) {
            float w[16];
#pragma unroll
            for (int kk = 0; kk < 16; kk++) w[kk] = W1[(kc + kk) * F1 + lane];
            for (int n0 = warp * 2; n0 < M; n0 += 2 * NWARPS) {
                st[lane] = xg[(size_t)(n0 + half) * DIN + kc + ln16];
                __syncwarp();
                float acc0, acc1;
                if (kc == 0) { acc0 = 0.f; acc1 = 0.f; }
                else { acc0 = xw[n0 * F1 + lane]; acc1 = xw[(n0 + 1) * F1 + lane]; }
                const float4* s4a = (const float4*)st;
                const float4* s4b = (const float4*)(st + 16);
#pragma unroll
                for (int q = 0; q < 4; q++) {
                    float4 a = s4a[q], b = s4b[q];
                    acc0 = fmaf(a.x, w[4*q+0], acc0); acc1 = fmaf(b.x, w[4*q+0], acc1);
                    acc0 = fmaf(a.y, w[4*q+1], acc0); acc1 = fmaf(b.y, w[4*q+1], acc1);
                    acc0 = fmaf(a.z, w[4*q+2], acc0); acc1 = fmaf(b.z, w[4*q+2], acc1);
                    acc0 = fmaf(a.w, w[4*q+3], acc0); acc1 = fmaf(b.w, w[4*q+3], acc1);
                }
                if (kc == DIN - 16) { acc0 *= dinv[n0]; acc1 *= dinv[n0 + 1]; }
                xw[n0 * F1 + lane] = acc0;
                xw[(n0 + 1) * F1 + lane] = acc1;
                __syncwarp();
            }
        }
    }
    __syncthreads();

    // ================= layers 1..3: agg (+ gemm) ============================
    agg32x2(hcat, xw, dinv, rp, col, b1, 0, lane, warp);
    __syncthreads();

    gemm32(hcat, xw, dinv, W2, 0, lane, warp);
    __syncthreads();
    agg32x2(hcat, xw, dinv, rp, col, b2, 32, lane, warp);
    __syncthreads();

    gemm32(hcat, xw, dinv, W3, 32, lane, warp);
    __syncthreads();
    agg32x2(hcat, xw, dinv, rp, col, b3, 64, lane, warp);
    __syncthreads();

    // ================= layer 4 (32 -> 1) ====================================
    {
        float* xwv = xw;                 // 1D [201]
        float w4 = W4[lane];
        for (int n = warp; n < M; n += NWARPS) {
            float v = hcat[n * FP + 64 + lane] * w4;
            v = warp_sum(v);
            if (lane == 0) xwv[n] = v * dinv[n];
        }
        if (tid == 0) xwv[200] = 0.f;
        __syncthreads();

        float bb = b4[0];
        for (int n = warp; n < M; n += NWARPS) {
            int e0 = rp[n], e1 = rp[n + 1];
            float a = 0.f;
            for (int e = e0 + lane; e < e1; e += 32) a += xwv[col[e]];
            a = warp_sum(a);
            if (lane == 0)
                hcat[n * FP + 96] = tanhf(fmaf(dinv[n], a + xwv[n], bb));
        }
        __syncthreads();
    }

    // ============ stage conv1 weights + SortPool (overlapped) ===============
    for (int i = tid; i < 16 * 97; i += NTHREADS) cW1s[i] = cW1[i];

    if (tid < M) {
        const int n = tid;
        float key = hcat[n * FP + 96];
        int r = 0;
        for (int j = 0; j < M; j++) {
            float kj = hcat[j * FP + 96];
            r += (kj > key) || (kj == key && j < n);
        }
        if (r < TOPK) topn[r] = n;
    }
    __syncthreads();

    // ================= conv1: warp per (o,k) dot of length 97 ===============
    for (int t = warp; t < 16 * TOPK; t += NWARPS) {
        int o = t & 15, k = t >> 4;
        const float* hr = hcat + topn[k] * FP;
        const float* wr = cW1s + o * 97;
        float a = 0.f;
#pragma unroll
        for (int q = 0; q < 3; q++)
            a = fmaf(wr[lane + 32 * q], hr[lane + 32 * q], a);
        if (lane == 0) a = fmaf(wr[96], hr[96], a);
        a = warp_sum(a);
        if (lane == 0) dots[k * 16 + o] = a + cb1[o];
    }
    __syncthreads();

    // relu + MaxPool1d(2,2) -> c1p[16][15]
    for (int idx = tid; idx < 16 * 15; idx += NTHREADS) {
        int o = idx / 15, p = idx % 15;
        float v0 = fmaxf(dots[(2 * p) * 16 + o], 0.f);
        float v1 = fmaxf(dots[(2 * p + 1) * 16 + o], 0.f);
        c1p[o * 15 + p] = fmaxf(v0, v1);
    }
    __syncthreads();

    // ================= conv2 (16->32, k=5) + relu -> flat[352] ==============
    for (int idx = tid; idx < 32 * 11; idx += NTHREADS) {
        int o = idx / 11, p = idx % 11;
        float acc = cb2[o];
#pragma unroll
        for (int i = 0; i < 16; i++)
#pragma unroll
            for (int t = 0; t < 5; t++)
                acc = fmaf(c1p[i * 15 + p + t], cW2[(o * 16 + i) * 5 + t], acc);
        flat[o * 11 + p] = fmaxf(acc, 0.f);
    }
    __syncthreads();

    // ================= linear1 (352 -> 128) + relu ==========================
    for (int j = tid; j < 128; j += NTHREADS) {
        float acc = lb1[j];
        for (int i = 0; i < 352; i++)
            acc = fmaf(flat[i], lW1[i * 128 + j], acc);
        hlin[j] = fmaxf(acc, 0.f);
    }
    __syncthreads();

    // ================= linear2 (128 -> 1) + sigmoid =========================
    if (warp == 0) {
        float v = 0.f;
#pragma unroll
        for (int r = 0; r < 4; r++)
            v = fmaf(hlin[r * 32 + lane], lW2[r * 32 + lane], v);
        v = warp_sum(v);
        if (lane == 0)
            out[g] = 1.0f / (1.0f + expf(-(v + lb2[0])));
    }
}

extern "C" void kernel_launch(void* const* d_in, const int* in_sizes, int n_in,
                              void* d_out, int out_size)
{
    const float* x   = (const float*)d_in[0];
    const int*   ei  = (const int*)  d_in[1];
    const float* W1  = (const float*)d_in[3];
    const float* b1  = (const float*)d_in[4];
    const float* W2  = (const float*)d_in[5];
    const float* b2  = (const float*)d_in[6];
    const float* W3  = (const float*)d_in[7];
    const float* b3  = (const float*)d_in[8];
    const float* W4  = (const float*)d_in[9];
    const float* b4  = (const float*)d_in[10];
    const float* cW1 = (const float*)d_in[11];
    const float* cb1 = (const float*)d_in[12];
    const float* cW2 = (const float*)d_in[13];
    const float* cb2 = (const float*)d_in[14];
    const float* lW1 = (const float*)d_in[15];
    const float* lb1 = (const float*)d_in[16];
    const float* lW2 = (const float*)d_in[17];
    const float* lb2 = (const float*)d_in[18];

    int Etot = in_sizes[1] / 2;

    cudaFuncSetAttribute(dgcnn_kernel,
                         cudaFuncAttributeMaxDynamicSharedMemorySize, SMEM_TOTAL);

    dgcnn_kernel<<<Bg, NTHREADS, SMEM_TOTAL>>>(
        x, ei, W1, b1, W2, b2, W3, b3, W4, b4,
        cW1, cb1, cW2, cb2, lW1, lb1, lW2, lb2,
        (float*)d_out, Etot);
}

// round 10
// speedup vs baseline: 1.0824x; 1.0824x over previous
#include <cuda_runtime.h>
#include <math.h>

// ---------------------------------------------------------------------------
// DGCNN fused per-graph kernel, v5.
// One CTA = one graph (200 nodes, 6400 edges). 384 threads, 2 CTAs/SM.
// v5: single-pass smem-atomic CSR (staging + pack, half the atomics),
//     8-padded CSR rows, 8-edge agg unroll with 4 accumulator chains.
// ---------------------------------------------------------------------------

#define NTHREADS 384
#define NWARPS   12

typedef unsigned long long ull;

constexpr int Bg   = 512;    // graphs
constexpr int M    = 200;    // nodes / graph
constexpr int EPG  = 6400;   // edges / graph
constexpr int DIN  = 128;
constexpr int F1   = 32;
constexpr int FP   = 100;    // padded feature row stride (16B align)
constexpr int TOPK = 30;
constexpr int DMAX = 80;     // staging capacity per node (deg ~32±5.7)

// Persistent SMEM layout (bytes)
constexpr int OFF_HCAT = 0;             // 200*100*4 = 80000
constexpr int OFF_XW   = 80000;         // 201*32*4  = 25728 -> 105728
constexpr int OFF_DINV = 105728;        // 200*4     -> 106528
constexpr int OFF_RP   = 106528;        // 201*4     -> pad 107344
constexpr int OFF_COL  = 107344;        // 8064 (8-padded: <=6400+200*7=7800)
constexpr int SMEM_TOTAL = 107344 + 8064;   // 115408 (2 CTAs: 230816 <= 228KB+)

// Aliases inside hcat region (dead until layer-1 agg writes hcat):
//  colFixed[200*80] -> hcat + 0      (CSR staging, dead after pack)
//  cnt[200] ints    -> hcat + 16000  (atomic counters / degrees)
//  stage            -> hcat + 17408  (layer-1 GEMM, 12 warps * 32 floats)
// Aliases inside xw region (xw used only as [201] floats by layer 4):
constexpr int OFF_TOP  = OFF_XW + 2048;   // 30 ints
constexpr int OFF_DOT  = OFF_XW + 2176;   // 480 floats
constexpr int OFF_C1P  = OFF_XW + 4096;   // 240 floats
constexpr int OFF_FLAT = OFF_XW + 5120;   // 352 floats
constexpr int OFF_HLIN = OFF_XW + 6592;   // 128 floats
constexpr int OFF_CW1S = OFF_XW + 7168;   // 16*97 floats

#define ADDX2(acc, v) \
    asm("add.rn.f32x2 %0, %0, %1;" : "+l"(acc) : "l"(v))
#define FMAX2(r, a, b, c) \
    asm("fma.rn.f32x2 %0, %1, %2, %3;" : "=l"(r) : "l"(a), "l"(b), "l"(c))

__device__ __forceinline__ ull pack2(float lo, float hi) {
    ull r;
    asm("mov.b64 %0, {%1, %2};" : "=l"(r)
        : "r"(__float_as_uint(lo)), "r"(__float_as_uint(hi)));
    return r;
}
__device__ __forceinline__ void unpack2(ull v, float& lo, float& hi) {
    unsigned a, b;
    asm("mov.b64 {%0, %1}, %2;" : "=r"(a), "=r"(b) : "l"(v));
    lo = __uint_as_float(a); hi = __uint_as_float(b);
}

__device__ __forceinline__ float warp_sum(float v) {
#pragma unroll
    for (int d = 16; d; d >>= 1) v += __shfl_xor_sync(0xffffffffu, v, d);
    return v;
}

// Half-warp f32x2 aggregation: lanes 0-15 -> node n, lanes 16-31 -> node n+1.
// Each lane owns channels (2*ln, 2*ln+1). xw pre-scaled by dinv[src].
// CSR rows are 8-padded (dummy node 200 has a zero xw row).
__device__ __forceinline__ void agg32x2(
    float* __restrict__ hcat, const float* __restrict__ xw,
    const float* __restrict__ dinv, const int* __restrict__ rp,
    const unsigned char* __restrict__ col,
    const float* __restrict__ bias, int outoff, int lane, int warp)
{
    const int half = lane >> 4;
    const int ln   = lane & 15;
    const ull bb2  = *(const ull*)(bias + 2 * ln);

    for (int n = 2 * warp + half; n < M; n += 2 * NWARPS) {
        const int e0 = rp[n], e1 = rp[n + 1];
        ull a0 = *(const ull*)(xw + n * F1 + 2 * ln);   // self term
        ull a1 = 0, a2 = 0, a3 = 0;
        for (int e = e0; e < e1; e += 8) {
            uchar4 ca = *(const uchar4*)(col + e);
            uchar4 cb = *(const uchar4*)(col + e + 4);
            ADDX2(a0, *(const ull*)(xw + ca.x * F1 + 2 * ln));
            ADDX2(a1, *(const ull*)(xw + ca.y * F1 + 2 * ln));
            ADDX2(a2, *(const ull*)(xw + ca.z * F1 + 2 * ln));
            ADDX2(a3, *(const ull*)(xw + ca.w * F1 + 2 * ln));
            ADDX2(a0, *(const ull*)(xw + cb.x * F1 + 2 * ln));
            ADDX2(a1, *(const ull*)(xw + cb.y * F1 + 2 * ln));
            ADDX2(a2, *(const ull*)(xw + cb.z * F1 + 2 * ln));
            ADDX2(a3, *(const ull*)(xw + cb.w * F1 + 2 * ln));
        }
        ADDX2(a0, a1);
        ADDX2(a2, a3);
        ADDX2(a0, a2);
        float dn = dinv[n];
        ull dn2 = pack2(dn, dn);
        ull r; FMAX2(r, dn2, a0, bb2);
        float lo, hi; unpack2(r, lo, hi);
        float2 o; o.x = tanhf(lo); o.y = tanhf(hi);
        *(float2*)(hcat + n * FP + outoff + 2 * ln) = o;
    }
}

// 32->32 GEMM in two 16-wide k chunks (16 weight regs live at a time).
__device__ __forceinline__ void gemm32(
    const float* __restrict__ hcat, float* __restrict__ xw,
    const float* __restrict__ dinv, const float* __restrict__ W,
    int inoff, int lane, int warp)
{
#pragma unroll
    for (int kc = 0; kc < 32; kc += 16) {
        float w[16];
#pragma unroll
        for (int k = 0; k < 16; k++) w[k] = W[(kc + k) * 32 + lane];
        for (int n = warp; n < M; n += NWARPS) {
            const float4* hr4 = (const float4*)(hcat + n * FP + inoff + kc);
            float acc = (kc == 0) ? 0.f : xw[n * F1 + lane];
#pragma unroll
            for (int q = 0; q < 4; q++) {
                float4 h = hr4[q];
                acc = fmaf(h.x, w[4 * q + 0], acc);
                acc = fmaf(h.y, w[4 * q + 1], acc);
                acc = fmaf(h.z, w[4 * q + 2], acc);
                acc = fmaf(h.w, w[4 * q + 3], acc);
            }
            if (kc == 16) acc *= dinv[n];
            xw[n * F1 + lane] = acc;
        }
    }
}

__global__ __launch_bounds__(NTHREADS, 2)
void dgcnn_kernel(
    const float* __restrict__ x,
    const int*   __restrict__ ei,       // [2, E]
    const float* __restrict__ W1, const float* __restrict__ b1,
    const float* __restrict__ W2, const float* __restrict__ b2,
    const float* __restrict__ W3, const float* __restrict__ b3,
    const float* __restrict__ W4, const float* __restrict__ b4,
    const float* __restrict__ cW1, const float* __restrict__ cb1,
    const float* __restrict__ cW2, const float* __restrict__ cb2,
    const float* __restrict__ lW1, const float* __restrict__ lb1,
    const float* __restrict__ lW2, const float* __restrict__ lb2,
    float* __restrict__ out, int Etot)
{
    extern __shared__ char smem[];
    float* hcat  = (float*)(smem + OFF_HCAT);
    float* xw    = (float*)(smem + OFF_XW);
    float* dinv  = (float*)(smem + OFF_DINV);
    int*   rp    = (int*)  (smem + OFF_RP);
    unsigned char* col = (unsigned char*)(smem + OFF_COL);
    unsigned char* colFixed = (unsigned char*)(smem);            // alias
    int*   cnt   = (int*)  (smem + 16000);                       // alias
    float* stage = (float*)(smem + 17408);                       // alias
    int*   topn  = (int*)  (smem + OFF_TOP);
    float* dots  = (float*)(smem + OFF_DOT);
    float* c1p   = (float*)(smem + OFF_C1P);
    float* flat  = (float*)(smem + OFF_FLAT);
    float* hlin  = (float*)(smem + OFF_HLIN);
    float* cW1s  = (float*)(smem + OFF_CW1S);

    const int g     = blockIdx.x;
    const int tid   = threadIdx.x;
    const int lane  = tid & 31;
    const int warp  = tid >> 5;
    const int nbase = g * M;
    const int ebase = g * EPG;

    const int2* s2 = (const int2*)(ei + ebase);
    const int2* d2 = (const int2*)(ei + Etot + ebase);

    // ====== CSR build: ONE atomic pass into 80-padded staging, then pack ====
    for (int i = tid; i < M; i += NTHREADS) cnt[i] = 0;
    __syncthreads();

    for (int e2 = tid; e2 < EPG / 2; e2 += NTHREADS) {
        int2 s = s2[e2];
        int2 d = d2[e2];
        int d0 = d.x - nbase, d1 = d.y - nbase;
        int p0 = atomicAdd(&cnt[d0], 1);
        colFixed[d0 * DMAX + p0] = (unsigned char)(s.x - nbase);
        int p1 = atomicAdd(&cnt[d1], 1);
        colFixed[d1 * DMAX + p1] = (unsigned char)(s.y - nbase);
    }
    __syncthreads();

    // degrees -> dinv
    for (int i = tid; i < M; i += NTHREADS)
        dinv[i] = rsqrtf((float)cnt[i] + 1.0f);

    // rowptr: exclusive scan of 8-padded degrees (warp 0)
    if (warp == 0) {
        int run = 0;
        for (int c0 = 0; c0 < 224; c0 += 32) {
            int i = c0 + lane;
            int v = (i < M) ? ((cnt[i] + 7) & ~7) : 0;
            int orig = v;
#pragma unroll
            for (int d = 1; d < 32; d <<= 1) {
                int t = __shfl_up_sync(0xffffffffu, v, d);
                if (lane >= d) v += t;
            }
            if (i < M) rp[i] = run + v - orig;
            run += __shfl_sync(0xffffffffu, v, 31);
        }
        if (lane == 0) rp[M] = run;
    }
    __syncthreads();

    // pack staging -> 8-padded CSR (dummy node 200 in tails)
    for (int n = warp; n < M; n += NWARPS) {
        int dg   = cnt[n];
        int base = rp[n];
        int dpad = rp[n + 1] - base;
        for (int l = lane; l < dpad; l += 32)
            col[base + l] = (l < dg) ? colFixed[n * DMAX + l]
                                     : (unsigned char)200;
    }
    if (tid < 32) xw[200 * F1 + lane] = 0.f;    // zero dummy xw row
    __syncthreads();

    // ================= layer-1 GEMM: xw' = dinv * (x[g] @ W1) ===============
    {
        const float* xg = x + (size_t)nbase * DIN;
        float* st = stage + warp * 32;
        const int half = lane >> 4, ln16 = lane & 15;
#pragma unroll
        for (int kc = 0; kc < DIN; kc += 16) {
            float w[16];
#pragma unroll
            for (int kk = 0; kk < 16; kk++) w[kk] = W1[(kc + kk) * F1 + lane];
            for (int n0 = warp * 2; n0 < M; n0 += 2 * NWARPS) {
                st[lane] = xg[(size_t)(n0 + half) * DIN + kc + ln16];
                __syncwarp();
                float acc0, acc1;
                if (kc == 0) { acc0 = 0.f; acc1 = 0.f; }
                else { acc0 = xw[n0 * F1 + lane]; acc1 = xw[(n0 + 1) * F1 + lane]; }
                const float4* s4a = (const float4*)st;
                const float4* s4b = (const float4*)(st + 16);
#pragma unroll
                for (int q = 0; q < 4; q++) {
                    float4 a = s4a[q], b = s4b[q];
                    acc0 = fmaf(a.x, w[4*q+0], acc0); acc1 = fmaf(b.x, w[4*q+0], acc1);
                    acc0 = fmaf(a.y, w[4*q+1], acc0); acc1 = fmaf(b.y, w[4*q+1], acc1);
                    acc0 = fmaf(a.z, w[4*q+2], acc0); acc1 = fmaf(b.z, w[4*q+2], acc1);
                    acc0 = fmaf(a.w, w[4*q+3], acc0); acc1 = fmaf(b.w, w[4*q+3], acc1);
                }
                if (kc == DIN - 16) { acc0 *= dinv[n0]; acc1 *= dinv[n0 + 1]; }
                xw[n0 * F1 + lane] = acc0;
                xw[(n0 + 1) * F1 + lane] = acc1;
                __syncwarp();
            }
        }
    }
    __syncthreads();

    // ================= layers 1..3: agg (+ gemm) ============================
    agg32x2(hcat, xw, dinv, rp, col, b1, 0, lane, warp);
    __syncthreads();

    gemm32(hcat, xw, dinv, W2, 0, lane, warp);
    __syncthreads();
    agg32x2(hcat, xw, dinv, rp, col, b2, 32, lane, warp);
    __syncthreads();

    gemm32(hcat, xw, dinv, W3, 32, lane, warp);
    __syncthreads();
    agg32x2(hcat, xw, dinv, rp, col, b3, 64, lane, warp);
    __syncthreads();

    // ================= layer 4 (32 -> 1) ====================================
    {
        float* xwv = xw;                 // 1D [201]
        float w4 = W4[lane];
        for (int n = warp; n < M; n += NWARPS) {
            float v = hcat[n * FP + 64 + lane] * w4;
            v = warp_sum(v);
            if (lane == 0) xwv[n] = v * dinv[n];
        }
        if (tid == 0) xwv[200] = 0.f;
        __syncthreads();

        float bb = b4[0];
        for (int n = warp; n < M; n += NWARPS) {
            int e0 = rp[n], e1 = rp[n + 1];
            float a = 0.f;
            for (int e = e0 + lane; e < e1; e += 32) a += xwv[col[e]];
            a = warp_sum(a);
            if (lane == 0)
                hcat[n * FP + 96] = tanhf(fmaf(dinv[n], a + xwv[n], bb));
        }
        __syncthreads();
    }

    // ============ stage conv1 weights + SortPool (overlapped) ===============
    for (int i = tid; i < 16 * 97; i += NTHREADS) cW1s[i] = cW1[i];

    if (tid < M) {
        const int n = tid;
        float key = hcat[n * FP + 96];
        int r = 0;
        for (int j = 0; j < M; j++) {
            float kj = hcat[j * FP + 96];
            r += (kj > key) || (kj == key && j < n);
        }
        if (r < TOPK) topn[r] = n;
    }
    __syncthreads();

    // ================= conv1: warp per (o,k) dot of length 97 ===============
    for (int t = warp; t < 16 * TOPK; t += NWARPS) {
        int o = t & 15, k = t >> 4;
        const float* hr = hcat + topn[k] * FP;
        const float* wr = cW1s + o * 97;
        float a = 0.f;
#pragma unroll
        for (int q = 0; q < 3; q++)
            a = fmaf(wr[lane + 32 * q], hr[lane + 32 * q], a);
        if (lane == 0) a = fmaf(wr[96], hr[96], a);
        a = warp_sum(a);
        if (lane == 0) dots[k * 16 + o] = a + cb1[o];
    }
    __syncthreads();

    // relu + MaxPool1d(2,2) -> c1p[16][15]
    for (int idx = tid; idx < 16 * 15; idx += NTHREADS) {
        int o = idx / 15, p = idx % 15;
        float v0 = fmaxf(dots[(2 * p) * 16 + o], 0.f);
        float v1 = fmaxf(dots[(2 * p + 1) * 16 + o], 0.f);
        c1p[o * 15 + p] = fmaxf(v0, v1);
    }
    __syncthreads();

    // ================= conv2 (16->32, k=5) + relu -> flat[352] ==============
    for (int idx = tid; idx < 32 * 11; idx += NTHREADS) {
        int o = idx / 11, p = idx % 11;
        float acc = cb2[o];
#pragma unroll
        for (int i = 0; i < 16; i++)
#pragma unroll
            for (int t = 0; t < 5; t++)
                acc = fmaf(c1p[i * 15 + p + t], cW2[(o * 16 + i) * 5 + t], acc);
        flat[o * 11 + p] = fmaxf(acc, 0.f);
    }
    __syncthreads();

    // ================= linear1 (352 -> 128) + relu ==========================
    for (int j = tid; j < 128; j += NTHREADS) {
        float acc = lb1[j];
        for (int i = 0; i < 352; i++)
            acc = fmaf(flat[i], lW1[i * 128 + j], acc);
        hlin[j] = fmaxf(acc, 0.f);
    }
    __syncthreads();

    // ================= linear2 (128 -> 1) + sigmoid =========================
    if (warp == 0) {
        float v = 0.f;
#pragma unroll
        for (int r = 0; r < 4; r++)
            v = fmaf(hlin[r * 32 + lane], lW2[r * 32 + lane], v);
        v = warp_sum(v);
        if (lane == 0)
            out[g] = 1.0f / (1.0f + expf(-(v + lb2[0])));
    }
}

extern "C" void kernel_launch(void* const* d_in, const int* in_sizes, int n_in,
                              void* d_out, int out_size)
{
    const float* x   = (const float*)d_in[0];
    const int*   ei  = (const int*)  d_in[1];
    const float* W1  = (const float*)d_in[3];
    const float* b1  = (const float*)d_in[4];
    const float* W2  = (const float*)d_in[5];
    const float* b2  = (const float*)d_in[6];
    const float* W3  = (const float*)d_in[7];
    const float* b3  = (const float*)d_in[8];
    const float* W4  = (const float*)d_in[9];
    const float* b4  = (const float*)d_in[10];
    const float* cW1 = (const float*)d_in[11];
    const float* cb1 = (const float*)d_in[12];
    const float* cW2 = (const float*)d_in[13];
    const float* cb2 = (const float*)d_in[14];
    const float* lW1 = (const float*)d_in[15];
    const float* lb1 = (const float*)d_in[16];
    const float* lW2 = (const float*)d_in[17];
    const float* lb2 = (const float*)d_in[18];

    int Etot = in_sizes[1] / 2;

    cudaFuncSetAttribute(dgcnn_kernel,
                         cudaFuncAttributeMaxDynamicSharedMemorySize, SMEM_TOTAL);

    dgcnn_kernel<<<Bg, NTHREADS, SMEM_TOTAL>>>(
        x, ei, W1, b1, W2, b2, W3, b3, W4, b4,
        cW1, cb1, cW2, cb2, lW1, lb1, lW2, lb2,
        (float*)d_out, Etot);
}